// round 6
// baseline (speedup 1.0000x reference)
#include <cuda_runtime.h>
#include <math.h>

// Problem constants
#define B_  32
#define T_  32
#define I_  256
#define H_  512
#define NH_ 4
#define HS_ 64
#define MS_ 2048
#define O_  256
// derived
#define KG_ 1024        // ctrl_in (512) + H (512)
#define NG_ 2048        // 4*H, gate col index n = g*512 + j
#define NHP_ 516        // 4 heads * 129 used head outputs
#define HPROW_ 2115     // HS + MS + 3
#define NBLK 128
#define NBAR (3*T_)

// ---------------- scratch (device globals; no allocation allowed) ----------------
__device__ float g_WgT[KG_*NG_];              // [k][n]  8MB   (n = g*512+j)
__device__ float g_WhT[H_*NHP_];              // [k][n*129+p]  1MB
__device__ float g_WoT[(H_+NH_*HS_)*O_];      // [k][o]
__device__ float g_h[B_*H_];
__device__ float g_c[B_*H_];
__device__ float g_hp_part[32][B_][NHP_];     // 32 k-slices of head projection
__device__ float2 g_stats[B_][8][4];          // [b][key][mq] = {chunk max, chunk sumexp}
__device__ float g_read_part[T_][4][B_][NH_*HS_]; // per-mq read partials
__device__ float g_hist_h[T_][B_][H_];
__device__ float g_mem[B_][MS_][HS_];         // 16.7MB
__device__ int   g_bar[NBAR];

__device__ __forceinline__ float sigm_acc(float v) { return 1.f / (1.f + expf(-v)); }

// ---------------- software grid barrier (monotonic index, no reset) ----------------
__device__ __forceinline__ void gridbar(int idx) {
    __syncthreads();
    if (threadIdx.x == 0) {
        __threadfence();
        atomicAdd(&g_bar[idx], 1);
        while (*((volatile int*)&g_bar[idx]) < NBLK) { __nanosleep(32); }
        __threadfence();
    }
    __syncthreads();
}

// ---------------- prep kernels ----------------
__global__ void k_zero() {
    const int NMEM = B_*MS_*HS_;
    const int total = NMEM + 2*B_*H_ + NBAR;
    for (int i = blockIdx.x*blockDim.x+threadIdx.x; i < total; i += gridDim.x*blockDim.x) {
        if (i < NMEM)                   (&g_mem[0][0][0])[i] = 0.f;
        else if (i < NMEM + B_*H_)      g_h[i - NMEM] = 0.f;
        else if (i < NMEM + 2*B_*H_)    g_c[i - NMEM - B_*H_] = 0.f;
        else                            g_bar[i - NMEM - 2*B_*H_] = 0;
    }
}

// WgT[k][n] = A[n][k] where A = [W_ih | W_hh] rows (n is already the gate-col index).
__global__ void k_trA(const float* __restrict__ W_ih, const float* __restrict__ W_hh) {
    __shared__ float tile[32][33];
    const int bx = blockIdx.x * 32;   // k
    const int by = blockIdx.y * 32;   // n (gate rows)
    const int tx = threadIdx.x, ty = threadIdx.y;
    #pragma unroll
    for (int i = 0; i < 32; i += 8) {
        int row = by + ty + i, k = bx + tx;
        float v = (k < 512) ? W_ih[row*512 + k] : W_hh[row*512 + (k - 512)];
        tile[ty + i][tx] = v;
    }
    __syncthreads();
    #pragma unroll
    for (int i = 0; i < 32; i += 8) {
        int k = bx + ty + i, row = by + tx;
        g_WgT[(size_t)k * NG_ + row] = tile[tx][ty + i];
    }
}

// WhT[k][r] with r = n*129 + p over used head rows
__global__ void k_trH(const float* __restrict__ W_head) {
    __shared__ float tile[32][33];
    const int bx = blockIdx.x * 32;   // k (512)
    const int by = blockIdx.y * 32;   // r (516, guard)
    const int tx = threadIdx.x, ty = threadIdx.y;
    #pragma unroll
    for (int i = 0; i < 32; i += 8) {
        int r = by + ty + i, k = bx + tx;
        float v = 0.f;
        if (r < NHP_) {
            int n = r / 129, p = r % 129;
            v = W_head[(size_t)(n * HPROW_ + p) * 512 + k];
        }
        tile[ty + i][tx] = v;
    }
    __syncthreads();
    #pragma unroll
    for (int i = 0; i < 32; i += 8) {
        int k = bx + ty + i, r = by + tx;
        if (r < NHP_) g_WhT[(size_t)k * NHP_ + r] = tile[tx][ty + i];
    }
}

// WoT[k][o] = W_out[o][k]
__global__ void k_trO(const float* __restrict__ W_out) {
    __shared__ float tile[32][33];
    const int bx = blockIdx.x * 32;   // k (768)
    const int by = blockIdx.y * 32;   // o (256)
    const int tx = threadIdx.x, ty = threadIdx.y;
    #pragma unroll
    for (int i = 0; i < 32; i += 8) {
        int o = by + ty + i, k = bx + tx;
        tile[ty + i][tx] = W_out[o * (H_ + NH_*HS_) + k];
    }
    __syncthreads();
    #pragma unroll
    for (int i = 0; i < 32; i += 8) {
        int k = bx + ty + i, o = by + tx;
        g_WoT[(size_t)k * O_ + o] = tile[tx][ty + i];
    }
}

// ---------------- the persistent recurrence kernel ----------------
struct SmA {
    union {
        float v[1024][8];       // [k][b-local]   32KB
        float red[512][17];     // [out = b*64 + n_l][kq]   34.8KB
    } u;
    float h[16][8];             // [jj][b-local] h values for head partial
};
struct SmAttn  {
    float key[8][64];
    float stat[8][256];
    float gm[8], inv[8], ws[4];
    float sk[4][64];
    float wsm[8][512];
    float racc[8][4][64];
};
union SmU { SmA a; SmAttn at; };

__global__ __launch_bounds__(256, 1)
void k_steps(const float* __restrict__ x, const float* __restrict__ b_ih,
             const float* __restrict__ b_hh, const float* __restrict__ b_head) {
    __shared__ SmU sm;
    const int bid = blockIdx.x, tid = threadIdx.x;

    // Phase A partition: (jc: 16 j-cols) x (bc: 8 batches)
    const int jc = bid >> 2, bc = bid & 3;
    const int j0 = jc * 16, bA0 = bc * 8;
    const int nq = tid & 15, kq = tid >> 4;   // nq: 4 n-cols, kq: 64-k slice
    const int gA = nq >> 2;                   // gate group of this thread's cols
    const int jjA = (nq & 3) * 4;
    const size_t wcol = (size_t)gA * 512 + j0 + jjA;
    // Phase C/D partition
    const int ab = bid >> 2, mq = bid & 3;
    const int m0 = mq * 512;

    for (int t = 0; t < T_; ++t) {
        // ========== Phase A: gates GEMM (full k) + LSTM + head partial ==========
        {
            // load v tile [1024 k][8 b]
            #pragma unroll
            for (int e = 0; e < 32; ++e) {
                int idx = e * 256 + tid;
                int bb = idx >> 10, k = idx & 1023;
                int b = bA0 + bb;
                float vv;
                if (k < 256) {
                    vv = __ldg(&x[(b * T_ + t) * I_ + k]);
                } else if (k < 512) {
                    if (t == 0) vv = 0.f;
                    else {
                        int r = k - 256;
                        vv = __ldcg(&g_read_part[t-1][0][b][r]) + __ldcg(&g_read_part[t-1][1][b][r])
                           + __ldcg(&g_read_part[t-1][2][b][r]) + __ldcg(&g_read_part[t-1][3][b][r]);
                    }
                } else {
                    vv = __ldcg(&g_h[b * H_ + (k - 512)]);
                }
                sm.a.u.v[k][bb] = vv;
            }
            __syncthreads();
            float acc[8][4];
            #pragma unroll
            for (int bi = 0; bi < 8; ++bi)
                #pragma unroll
                for (int ni = 0; ni < 4; ++ni) acc[bi][ni] = 0.f;
            const float* wbase = &g_WgT[wcol];
            #pragma unroll 8
            for (int kk = 0; kk < 64; ++kk) {
                int k = kq * 64 + kk;
                float4 w4 = __ldcg((const float4*)(wbase + (size_t)k * NG_));
                float4 va = *(const float4*)&sm.a.u.v[k][0];
                float4 vb = *(const float4*)&sm.a.u.v[k][4];
                float vs[8] = {va.x, va.y, va.z, va.w, vb.x, vb.y, vb.z, vb.w};
                #pragma unroll
                for (int bi = 0; bi < 8; ++bi) {
                    acc[bi][0] += vs[bi] * w4.x;
                    acc[bi][1] += vs[bi] * w4.y;
                    acc[bi][2] += vs[bi] * w4.z;
                    acc[bi][3] += vs[bi] * w4.w;
                }
            }
            __syncthreads();   // v dead; red overlays it
            #pragma unroll
            for (int bi = 0; bi < 8; ++bi)
                #pragma unroll
                for (int ni = 0; ni < 4; ++ni)
                    sm.a.u.red[bi * 64 + nq * 4 + ni][kq] = acc[bi][ni];
            __syncthreads();
            // LSTM elementwise on reduced gates (128 cells: 8 b x 16 j)
            if (tid < 128) {
                const int bi = tid >> 4, jj = tid & 15;
                const int b = bA0 + bi, j = j0 + jj;
                float gs[4];
                #pragma unroll
                for (int g4 = 0; g4 < 4; ++g4) {
                    int out = bi * 64 + g4 * 16 + jj;
                    float s2 = 0.f;
                    #pragma unroll
                    for (int q = 0; q < 16; ++q) s2 += sm.a.u.red[out][q];
                    int n = g4 * 512 + j;
                    gs[g4] = s2 + __ldg(&b_ih[n]) + __ldg(&b_hh[n]);
                }
                float cold = g_c[b * H_ + j];
                float iv = sigm_acc(gs[0]), fv = sigm_acc(gs[1]);
                float gv = tanhf(gs[2]),   ov = sigm_acc(gs[3]);
                float cn = fv * cold + iv * gv;
                float hn = ov * tanhf(cn);
                g_c[b * H_ + j] = cn;
                g_h[b * H_ + j] = hn;
                g_hist_h[t][b][j] = hn;
                sm.a.h[jj][bi] = hn;
            }
            __syncthreads();
            // head projection partial over this block's 16 k (=j) values
            #pragma unroll
            for (int e = 0; e < 3; ++e) {
                int nn = e * 256 + tid;
                if (nn < NHP_) {
                    float a8[8];
                    #pragma unroll
                    for (int bi = 0; bi < 8; ++bi) a8[bi] = 0.f;
                    #pragma unroll
                    for (int k2 = 0; k2 < 16; ++k2) {
                        float w = __ldcg(&g_WhT[(size_t)(j0 + k2) * NHP_ + nn]);
                        #pragma unroll
                        for (int bi = 0; bi < 8; ++bi) a8[bi] += sm.a.h[k2][bi] * w;
                    }
                    #pragma unroll
                    for (int bi = 0; bi < 8; ++bi) g_hp_part[jc][bA0 + bi][nn] = a8[bi];
                }
            }
        }
        gridbar(3*t + 0);

        // ========== Phase C: key build (hp reduce) + scores + chunk stats ==========
        float s[2][8];
        {
            #pragma unroll
            for (int e = 0; e < 2; ++e) {
                int idx = e * 256 + tid;
                int key = idx >> 6, h = idx & 63;
                int n = key & 3;
                int p = (key < 4) ? h : 64 + h;
                int nn = n * 129 + p;
                float v = __ldg(&b_head[n * HPROW_ + p]);
                #pragma unroll 8
                for (int jc2 = 0; jc2 < 32; ++jc2) v += __ldcg(&g_hp_part[jc2][ab][nn]);
                sm.at.key[key][h] = v * 0.125f;   // fold 1/sqrt(HS)
            }
            __syncthreads();
            #pragma unroll
            for (int ms = 0; ms < 2; ++ms)
                #pragma unroll
                for (int key = 0; key < 8; ++key) s[ms][key] = 0.f;
            #pragma unroll
            for (int ms = 0; ms < 2; ++ms) {
                const int m = m0 + tid * 2 + ms;
                const float4* mp = (const float4*)&g_mem[ab][m][0];
                float4 r[16];
                #pragma unroll
                for (int i = 0; i < 16; ++i) r[i] = mp[i];
                #pragma unroll
                for (int hc = 0; hc < 16; ++hc) {
                    float4 mv = r[hc];
                    #pragma unroll
                    for (int key = 0; key < 8; ++key) {
                        float4 kk4 = *(const float4*)&sm.at.key[key][hc * 4];
                        s[ms][key] += kk4.x*mv.x + kk4.y*mv.y + kk4.z*mv.z + kk4.w*mv.w;
                    }
                }
            }
            #pragma unroll
            for (int key = 0; key < 8; ++key)
                sm.at.stat[key][tid] = fmaxf(s[0][key], s[1][key]);
            __syncthreads();
            {
                const int w = tid >> 5, l = tid & 31;
                float mx = -1e30f;
                for (int i = l; i < 256; i += 32) mx = fmaxf(mx, sm.at.stat[w][i]);
                #pragma unroll
                for (int sh = 16; sh; sh >>= 1) mx = fmaxf(mx, __shfl_xor_sync(0xffffffffu, mx, sh));
                if (l == 0) sm.at.gm[w] = mx;
            }
            __syncthreads();
            #pragma unroll
            for (int key = 0; key < 8; ++key)
                sm.at.stat[key][tid] = __expf(s[0][key] - sm.at.gm[key]) + __expf(s[1][key] - sm.at.gm[key]);
            __syncthreads();
            {
                const int w = tid >> 5, l = tid & 31;
                float se = 0.f;
                for (int i = l; i < 256; i += 32) se += sm.at.stat[w][i];
                #pragma unroll
                for (int sh = 16; sh; sh >>= 1) se += __shfl_xor_sync(0xffffffffu, se, sh);
                if (l == 0) g_stats[ab][w][mq] = make_float2(sm.at.gm[w], se);
            }
        }
        gridbar(3*t + 1);

        // ========== Phase D: softmax apply, read accumulate, memory update ==========
        {
            if (tid < 8) {
                float2 st0 = __ldcg(&g_stats[ab][tid][0]);
                float2 st1 = __ldcg(&g_stats[ab][tid][1]);
                float2 st2 = __ldcg(&g_stats[ab][tid][2]);
                float2 st3 = __ldcg(&g_stats[ab][tid][3]);
                float gm = fmaxf(fmaxf(st0.x, st1.x), fmaxf(st2.x, st3.x));
                float ssum = st0.y * __expf(st0.x - gm) + st1.y * __expf(st1.x - gm)
                           + st2.y * __expf(st2.x - gm) + st3.y * __expf(st3.x - gm);
                sm.at.gm[tid] = gm; sm.at.inv[tid] = 1.f / ssum;
            } else if (tid < 12) {
                int n = tid - 8;
                float v = __ldg(&b_head[n * HPROW_ + 128]);
                #pragma unroll 8
                for (int jc2 = 0; jc2 < 32; ++jc2) v += __ldcg(&g_hp_part[jc2][ab][n * 129 + 128]);
                sm.at.ws[n] = sigm_acc(v);
            }
            __syncthreads();
            {
                int n = tid >> 6, h = tid & 63;
                int nn = n * 129 + 64 + h;
                float v = __ldg(&b_head[n * HPROW_ + 64 + h]);
                #pragma unroll 8
                for (int jc2 = 0; jc2 < 32; ++jc2) v += __ldcg(&g_hp_part[jc2][ab][nn]);
                sm.at.sk[n][h] = v * sm.at.ws[n];
            }
            #pragma unroll
            for (int ms = 0; ms < 2; ++ms)
                #pragma unroll
                for (int key = 0; key < 8; ++key)
                    sm.at.wsm[key][tid * 2 + ms] = __expf(s[ms][key] - sm.at.gm[key]) * sm.at.inv[key];
            __syncthreads();

            const int w = tid >> 5, l = tid & 31;
            const int msub = l >> 3, hb = (l & 7) * 8;
            float skreg[4][8];
            #pragma unroll
            for (int n = 0; n < 4; ++n) {
                float4 a4 = *(const float4*)&sm.at.sk[n][hb];
                float4 c4 = *(const float4*)&sm.at.sk[n][hb + 4];
                skreg[n][0]=a4.x; skreg[n][1]=a4.y; skreg[n][2]=a4.z; skreg[n][3]=a4.w;
                skreg[n][4]=c4.x; skreg[n][5]=c4.y; skreg[n][6]=c4.z; skreg[n][7]=c4.w;
            }
            float racc[4][8];
            #pragma unroll
            for (int n = 0; n < 4; ++n)
                #pragma unroll
                for (int q = 0; q < 8; ++q) racc[n][q] = 0.f;
            #pragma unroll
            for (int it = 0; it < 16; ++it) {
                int ml = it * 32 + w * 4 + msub;
                int m = m0 + ml;
                float* mp = &g_mem[ab][m][hb];
                float4 a4 = *(const float4*)mp;
                float4 c4 = *(const float4*)(mp + 4);
                float mv[8] = {a4.x, a4.y, a4.z, a4.w, c4.x, c4.y, c4.z, c4.w};
                float rw[4], ww[4];
                #pragma unroll
                for (int n = 0; n < 4; ++n) { rw[n] = sm.at.wsm[n][ml]; ww[n] = sm.at.wsm[4 + n][ml]; }
                #pragma unroll
                for (int n = 0; n < 4; ++n)
                    #pragma unroll
                    for (int q = 0; q < 8; ++q) racc[n][q] += rw[n] * mv[q];
                #pragma unroll
                for (int q = 0; q < 8; ++q)
                    mv[q] += ww[0]*skreg[0][q] + ww[1]*skreg[1][q] + ww[2]*skreg[2][q] + ww[3]*skreg[3][q];
                a4.x=mv[0]; a4.y=mv[1]; a4.z=mv[2]; a4.w=mv[3];
                c4.x=mv[4]; c4.y=mv[5]; c4.z=mv[6]; c4.w=mv[7];
                *(float4*)mp = a4;
                *(float4*)(mp + 4) = c4;
            }
            #pragma unroll
            for (int n = 0; n < 4; ++n)
                #pragma unroll
                for (int q = 0; q < 8; ++q) {
                    racc[n][q] += __shfl_xor_sync(0xffffffffu, racc[n][q], 8);
                    racc[n][q] += __shfl_xor_sync(0xffffffffu, racc[n][q], 16);
                }
            if (l < 8) {
                #pragma unroll
                for (int n = 0; n < 4; ++n)
                    #pragma unroll
                    for (int q = 0; q < 8; ++q) sm.at.racc[w][n][hb + q] = racc[n][q];
            }
            __syncthreads();
            {
                int n = tid >> 6, h = tid & 63;
                float ssum = 0.f;
                #pragma unroll
                for (int wr = 0; wr < 8; ++wr) ssum += sm.at.racc[wr][n][h];
                g_read_part[t][mq][ab][n * 64 + h] = ssum;
            }
        }
        gridbar(3*t + 2);
    }
}

// ---------------- final output GEMM: outputs[b][t][o] ----------------
__global__ void k_out(const float* __restrict__ b_out, float* __restrict__ out) {
    const int m0 = blockIdx.x * 32, nc = blockIdx.y;
    const int tid = threadIdx.x;
    __shared__ float a_sh[32][64];
    const int n_l = tid & 63, mg = tid >> 6;
    const int n = nc * 64 + n_l;
    float acc[8];
    #pragma unroll
    for (int r = 0; r < 8; ++r) acc[r] = 0.f;
    for (int kt = 0; kt < 12; ++kt) {
        __syncthreads();
        #pragma unroll
        for (int e = 0; e < 8; ++e) {
            int lidx = e * 256 + tid;
            int mrow = lidx >> 6, kk = lidx & 63;
            int m = m0 + mrow;
            int ts = m >> 5, bb = m & 31;
            int gk = kt * 64 + kk;
            float v;
            if (gk < 512) v = g_hist_h[ts][bb][gk];
            else {
                int r = gk - 512;
                v = g_read_part[ts][0][bb][r] + g_read_part[ts][1][bb][r]
                  + g_read_part[ts][2][bb][r] + g_read_part[ts][3][bb][r];
            }
            a_sh[mrow][kk] = v;
        }
        __syncthreads();
        #pragma unroll 4
        for (int kk = 0; kk < 64; ++kk) {
            float wv = g_WoT[(kt * 64 + kk) * O_ + n];
            #pragma unroll
            for (int r = 0; r < 8; ++r) acc[r] += a_sh[mg * 8 + r][kk] * wv;
        }
    }
    float bo = b_out[n];
    #pragma unroll
    for (int r = 0; r < 8; ++r) {
        int m = m0 + mg * 8 + r;
        int ts = m >> 5, bb = m & 31;
        out[(bb * T_ + ts) * O_ + n] = acc[r] + bo;
    }
}

// ---------------- final state copy: mem, h, c into d_out ----------------
__global__ void k_final(float* __restrict__ out) {
    const int OUT_N = B_ * T_ * O_;            // 262144
    const int NMEM  = B_ * MS_ * HS_;          // 4194304
    const int total = NMEM + 2 * B_ * H_;
    for (int i = blockIdx.x * blockDim.x + threadIdx.x; i < total; i += gridDim.x * blockDim.x) {
        if (i < NMEM)                 out[OUT_N + i] = (&g_mem[0][0][0])[i];
        else if (i < NMEM + B_ * H_)  out[OUT_N + i] = g_h[i - NMEM];
        else                          out[OUT_N + i] = g_c[i - NMEM - B_ * H_];
    }
}

extern "C" void kernel_launch(void* const* d_in, const int* in_sizes, int n_in,
                              void* d_out, int out_size) {
    const float* x      = (const float*)d_in[0];
    const float* W_ih   = (const float*)d_in[1];
    const float* W_hh   = (const float*)d_in[2];
    const float* b_ih   = (const float*)d_in[3];
    const float* b_hh   = (const float*)d_in[4];
    const float* W_head = (const float*)d_in[5];
    const float* b_head = (const float*)d_in[6];
    const float* W_out  = (const float*)d_in[7];
    const float* b_out  = (const float*)d_in[8];
    float* out = (float*)d_out;

    k_zero<<<2048, 256>>>();
    k_trA<<<dim3(32, 64), dim3(32, 8)>>>(W_ih, W_hh);
    k_trH<<<dim3(16, 17), dim3(32, 8)>>>(W_head);
    k_trO<<<dim3(24, 8),  dim3(32, 8)>>>(W_out);
    k_steps<<<NBLK, 256>>>(x, b_ih, b_hh, b_head);
    k_out<<<dim3(32, 4), 256>>>(b_out, out);
    k_final<<<2048, 256>>>(out);
}

// round 7
// speedup vs baseline: 1.0719x; 1.0719x over previous
#include <cuda_runtime.h>
#include <math.h>

// Problem constants
#define B_  32
#define T_  32
#define I_  256
#define H_  512
#define NH_ 4
#define HS_ 64
#define MS_ 2048
#define O_  256
// derived
#define KG_ 1024        // ctrl_in (512) + H (512)
#define NG_ 2048        // 4*H, gate col index n = g*512 + j
#define NHP_ 516        // 4 heads * 129 used head outputs
#define HPROW_ 2115     // HS + MS + 3
#define NBLK 128
#define NBAR (4*T_)

// ---------------- scratch (device globals; no allocation allowed) ----------------
__device__ float g_WgT[KG_*NG_];              // [k][n]  8MB   (n = g*512+j)
__device__ float g_WhT[H_*NHP_];              // [k][n*129+p]  1MB
__device__ float g_WoT[(H_+NH_*HS_)*O_];      // [k][o]
__device__ float g_h[B_*H_];
__device__ float g_c[B_*H_];
__device__ float g_gates_part[8][B_][NG_];    // k-split (8) partial gates
__device__ float g_hp_part[16][B_][NHP_];     // k-split (16) partial head outputs
__device__ float2 g_stats[B_][8][4];          // [b][key][mq] = {chunk max, chunk sumexp}
__device__ float g_read_part[T_][4][B_][NH_*HS_]; // per-mq read partials
__device__ float g_hist_h[T_][B_][H_];
__device__ float g_mem[B_][MS_][HS_];         // 16.7MB
__device__ int   g_bar[NBAR];

__device__ __forceinline__ float sigm_acc(float v) { return 1.f / (1.f + expf(-v)); }

// ---------------- grid barrier: release-add + acquire-poll, NO L1 flush ----------------
// All cross-block data is read with __ldcg (L2), so no CCTL.IVALL is needed and
// block-private data (mem slices, c) stays L1-resident across the whole loop.
__device__ __forceinline__ void gridbar(int idx) {
    __syncthreads();
    if (threadIdx.x == 0) {
        int* p = &g_bar[idx];
        asm volatile("red.release.gpu.global.add.s32 [%0], 1;" :: "l"(p) : "memory");
        int v;
        do {
            asm volatile("ld.acquire.gpu.global.s32 %0, [%1];" : "=r"(v) : "l"(p) : "memory");
        } while (v < NBLK);
    }
    __syncthreads();
}

// ---------------- prep kernels ----------------
__global__ void k_zero() {
    const int NMEM = B_*MS_*HS_;
    const int total = NMEM + 2*B_*H_ + NBAR;
    for (int i = blockIdx.x*blockDim.x+threadIdx.x; i < total; i += gridDim.x*blockDim.x) {
        if (i < NMEM)                   (&g_mem[0][0][0])[i] = 0.f;
        else if (i < NMEM + B_*H_)      g_h[i - NMEM] = 0.f;
        else if (i < NMEM + 2*B_*H_)    g_c[i - NMEM - B_*H_] = 0.f;
        else                            g_bar[i - NMEM - 2*B_*H_] = 0;
    }
}

// WgT[k][n] = A[n][k] where A = [W_ih | W_hh] rows (n is already the gate-col index).
__global__ void k_trA(const float* __restrict__ W_ih, const float* __restrict__ W_hh) {
    __shared__ float tile[32][33];
    const int bx = blockIdx.x * 32;   // k
    const int by = blockIdx.y * 32;   // n (gate rows)
    const int tx = threadIdx.x, ty = threadIdx.y;
    #pragma unroll
    for (int i = 0; i < 32; i += 8) {
        int row = by + ty + i, k = bx + tx;
        float v = (k < 512) ? W_ih[row*512 + k] : W_hh[row*512 + (k - 512)];
        tile[ty + i][tx] = v;
    }
    __syncthreads();
    #pragma unroll
    for (int i = 0; i < 32; i += 8) {
        int k = bx + ty + i, row = by + tx;
        g_WgT[(size_t)k * NG_ + row] = tile[tx][ty + i];
    }
}

// WhT[k][r] with r = n*129 + p over used head rows
__global__ void k_trH(const float* __restrict__ W_head) {
    __shared__ float tile[32][33];
    const int bx = blockIdx.x * 32;   // k (512)
    const int by = blockIdx.y * 32;   // r (516, guard)
    const int tx = threadIdx.x, ty = threadIdx.y;
    #pragma unroll
    for (int i = 0; i < 32; i += 8) {
        int r = by + ty + i, k = bx + tx;
        float v = 0.f;
        if (r < NHP_) {
            int n = r / 129, p = r % 129;
            v = W_head[(size_t)(n * HPROW_ + p) * 512 + k];
        }
        tile[ty + i][tx] = v;
    }
    __syncthreads();
    #pragma unroll
    for (int i = 0; i < 32; i += 8) {
        int k = bx + ty + i, r = by + tx;
        if (r < NHP_) g_WhT[(size_t)k * NHP_ + r] = tile[tx][ty + i];
    }
}

// WoT[k][o] = W_out[o][k]
__global__ void k_trO(const float* __restrict__ W_out) {
    __shared__ float tile[32][33];
    const int bx = blockIdx.x * 32;   // k (768)
    const int by = blockIdx.y * 32;   // o (256)
    const int tx = threadIdx.x, ty = threadIdx.y;
    #pragma unroll
    for (int i = 0; i < 32; i += 8) {
        int o = by + ty + i, k = bx + tx;
        tile[ty + i][tx] = W_out[o * (H_ + NH_*HS_) + k];
    }
    __syncthreads();
    #pragma unroll
    for (int i = 0; i < 32; i += 8) {
        int k = bx + ty + i, o = by + tx;
        g_WoT[(size_t)k * O_ + o] = tile[tx][ty + i];
    }
}

// ---------------- the persistent recurrence kernel ----------------
struct SmGates { float v[128][32]; float w[32][128]; };
struct SmP2    { float h[4][32]; };
struct SmAttn  {
    float key[8][64];
    float stat[8][256];
    float gm[8], inv[8], ws[4];
    float sk[4][64];
    float wsm[8][512];
    float racc[8][4][64];
};
union SmU { SmGates g; SmP2 p2; SmAttn a; };

__global__ __launch_bounds__(256, 1)
void k_steps(const float* __restrict__ x, const float* __restrict__ b_ih,
             const float* __restrict__ b_hh, const float* __restrict__ b_head) {
    __shared__ SmU sm;
    const int bid = blockIdx.x, tid = threadIdx.x;

    // P1 partition
    const int nc = bid >> 3, ksg = bid & 7;
    const int n0 = nc * 128, k0g = ksg * 128;
    const int n4 = tid & 31, bq = tid >> 5;
    const int b0v = bq * 4;
    // P2 partition
    const int bq2 = bid >> 4, ks2 = bid & 15;
    const int b02 = bq2 * 4, j0 = ks2 * 32;
    // P3/P4 partition
    const int ab = bid >> 2, mq = bid & 3;
    const int m0 = mq * 512;

    for (int t = 0; t < T_; ++t) {
        // ================= P1: gates GEMM (partials over 8 k-slices) =================
        {
            float acc[4][4];
            #pragma unroll
            for (int bi = 0; bi < 4; ++bi)
                #pragma unroll
                for (int ni = 0; ni < 4; ++ni) acc[bi][ni] = 0.f;
            // load v tile [128k][32b]
            #pragma unroll
            for (int e = 0; e < 16; ++e) {
                int idx = e * 256 + tid;
                int kk = idx >> 5, bb = idx & 31;
                int gk = k0g + kk;
                float vv;
                if (gk < 256) {
                    vv = __ldg(&x[(bb * T_ + t) * I_ + gk]);
                } else if (gk < 512) {
                    if (t == 0) vv = 0.f;
                    else {
                        int r = gk - 256;
                        vv = __ldcg(&g_read_part[t-1][0][bb][r]) + __ldcg(&g_read_part[t-1][1][bb][r])
                           + __ldcg(&g_read_part[t-1][2][bb][r]) + __ldcg(&g_read_part[t-1][3][bb][r]);
                    }
                } else {
                    vv = __ldcg(&g_h[bb * H_ + (gk - 512)]);
                }
                sm.g.v[kk][bb] = vv;
            }
            for (int c = 0; c < 4; ++c) {
                __syncthreads();
                #pragma unroll
                for (int e = 0; e < 4; ++e) {
                    int lin = e * 1024 + tid * 4;
                    int row = lin >> 7, col = lin & 127;
                    *(float4*)&sm.g.w[row][col] =
                        __ldcg((const float4*)&g_WgT[(size_t)(k0g + c*32 + row) * NG_ + n0 + col]);
                }
                __syncthreads();
                #pragma unroll
                for (int kk = 0; kk < 32; ++kk) {
                    float4 v4 = *(const float4*)&sm.g.v[c*32 + kk][b0v];
                    float4 w4 = *(const float4*)&sm.g.w[kk][n4 * 4];
                    acc[0][0] += v4.x*w4.x; acc[0][1] += v4.x*w4.y; acc[0][2] += v4.x*w4.z; acc[0][3] += v4.x*w4.w;
                    acc[1][0] += v4.y*w4.x; acc[1][1] += v4.y*w4.y; acc[1][2] += v4.y*w4.z; acc[1][3] += v4.y*w4.w;
                    acc[2][0] += v4.z*w4.x; acc[2][1] += v4.z*w4.y; acc[2][2] += v4.z*w4.z; acc[2][3] += v4.z*w4.w;
                    acc[3][0] += v4.w*w4.x; acc[3][1] += v4.w*w4.y; acc[3][2] += v4.w*w4.z; acc[3][3] += v4.w*w4.w;
                }
            }
            const int col0 = n0 + n4 * 4;
            if (ksg == 0) {
                float4 bi4 = make_float4(b_ih[col0] + b_hh[col0],
                                         b_ih[col0+1] + b_hh[col0+1],
                                         b_ih[col0+2] + b_hh[col0+2],
                                         b_ih[col0+3] + b_hh[col0+3]);
                #pragma unroll
                for (int bi = 0; bi < 4; ++bi) {
                    acc[bi][0] += bi4.x; acc[bi][1] += bi4.y; acc[bi][2] += bi4.z; acc[bi][3] += bi4.w;
                }
            }
            #pragma unroll
            for (int bi = 0; bi < 4; ++bi) {
                float4 o4 = make_float4(acc[bi][0], acc[bi][1], acc[bi][2], acc[bi][3]);
                *(float4*)&g_gates_part[ksg][b0v + bi][col0] = o4;
            }
        }
        gridbar(4*t + 0);

        // ================= P2: LSTM elementwise + partial head GEMM =================
        {
            if (tid < 128) {
                int bi = tid >> 5, jj = tid & 31;
                int b = b02 + bi, j = j0 + jj;
                float gi = 0.f, gf = 0.f, gg = 0.f, go = 0.f;
                #pragma unroll
                for (int p = 0; p < 8; ++p) {
                    gi += __ldcg(&g_gates_part[p][b][j]);
                    gf += __ldcg(&g_gates_part[p][b][512 + j]);
                    gg += __ldcg(&g_gates_part[p][b][1024 + j]);
                    go += __ldcg(&g_gates_part[p][b][1536 + j]);
                }
                float cold = g_c[b * H_ + j];
                float iv = sigm_acc(gi), fv = sigm_acc(gf);
                float gv = tanhf(gg),   ov = sigm_acc(go);
                float cn = fv * cold + iv * gv;
                float hn = ov * tanhf(cn);
                g_c[b * H_ + j] = cn;
                g_h[b * H_ + j] = hn;
                g_hist_h[t][b][j] = hn;
                sm.p2.h[bi][jj] = hn;
            }
            __syncthreads();
            #pragma unroll
            for (int e = 0; e < 3; ++e) {
                int nn = tid + e * 256;
                if (nn < NHP_) {
                    float a0 = 0.f, a1 = 0.f, a2 = 0.f, a3 = 0.f;
                    #pragma unroll
                    for (int k = 0; k < 32; ++k) {
                        float w = __ldcg(&g_WhT[(size_t)(j0 + k) * NHP_ + nn]);
                        a0 += sm.p2.h[0][k] * w;
                        a1 += sm.p2.h[1][k] * w;
                        a2 += sm.p2.h[2][k] * w;
                        a3 += sm.p2.h[3][k] * w;
                    }
                    g_hp_part[ks2][b02 + 0][nn] = a0;
                    g_hp_part[ks2][b02 + 1][nn] = a1;
                    g_hp_part[ks2][b02 + 2][nn] = a2;
                    g_hp_part[ks2][b02 + 3][nn] = a3;
                }
            }
        }
        gridbar(4*t + 1);

        // ================= P3: attention scores (kept in registers) =================
        float s[2][8];
        {
            #pragma unroll
            for (int e = 0; e < 2; ++e) {
                int idx = e * 256 + tid;
                int key = idx >> 6, h = idx & 63;
                int n = key & 3;
                int p = (key < 4) ? h : 64 + h;
                float v = __ldg(&b_head[n * HPROW_ + p]);
                #pragma unroll
                for (int ps = 0; ps < 16; ++ps) v += __ldcg(&g_hp_part[ps][ab][n * 129 + p]);
                sm.a.key[key][h] = v * 0.125f;   // fold 1/sqrt(HS)
            }
            __syncthreads();
            #pragma unroll
            for (int ms = 0; ms < 2; ++ms)
                #pragma unroll
                for (int key = 0; key < 8; ++key) s[ms][key] = 0.f;
            #pragma unroll
            for (int ms = 0; ms < 2; ++ms) {
                const int m = m0 + tid * 2 + ms;
                const float4* mp = (const float4*)&g_mem[ab][m][0];   // block-private: L1-warm
                float4 r[16];
                #pragma unroll
                for (int i = 0; i < 16; ++i) r[i] = mp[i];
                #pragma unroll
                for (int hc = 0; hc < 16; ++hc) {
                    float4 mv = r[hc];
                    #pragma unroll
                    for (int key = 0; key < 8; ++key) {
                        float4 kq = *(const float4*)&sm.a.key[key][hc * 4];
                        s[ms][key] += kq.x*mv.x + kq.y*mv.y + kq.z*mv.z + kq.w*mv.w;
                    }
                }
            }
            // chunk stats: max
            #pragma unroll
            for (int key = 0; key < 8; ++key)
                sm.a.stat[key][tid] = fmaxf(s[0][key], s[1][key]);
            __syncthreads();
            {
                const int w = tid >> 5, l = tid & 31;
                float mx = -1e30f;
                for (int i = l; i < 256; i += 32) mx = fmaxf(mx, sm.a.stat[w][i]);
                #pragma unroll
                for (int sh = 16; sh; sh >>= 1) mx = fmaxf(mx, __shfl_xor_sync(0xffffffffu, mx, sh));
                if (l == 0) sm.a.gm[w] = mx;
            }
            __syncthreads();
            #pragma unroll
            for (int key = 0; key < 8; ++key)
                sm.a.stat[key][tid] = __expf(s[0][key] - sm.a.gm[key]) + __expf(s[1][key] - sm.a.gm[key]);
            __syncthreads();
            {
                const int w = tid >> 5, l = tid & 31;
                float se = 0.f;
                for (int i = l; i < 256; i += 32) se += sm.a.stat[w][i];
                #pragma unroll
                for (int sh = 16; sh; sh >>= 1) se += __shfl_xor_sync(0xffffffffu, se, sh);
                if (l == 0) g_stats[ab][w][mq] = make_float2(sm.a.gm[w], se);
            }
        }
        gridbar(4*t + 2);

        // ================= P4: softmax apply, read accumulate, memory update =================
        {
            if (tid < 8) {
                float2 st0 = __ldcg(&g_stats[ab][tid][0]);
                float2 st1 = __ldcg(&g_stats[ab][tid][1]);
                float2 st2 = __ldcg(&g_stats[ab][tid][2]);
                float2 st3 = __ldcg(&g_stats[ab][tid][3]);
                float gm = fmaxf(fmaxf(st0.x, st1.x), fmaxf(st2.x, st3.x));
                float ssum = st0.y * __expf(st0.x - gm) + st1.y * __expf(st1.x - gm)
                           + st2.y * __expf(st2.x - gm) + st3.y * __expf(st3.x - gm);
                sm.a.gm[tid] = gm; sm.a.inv[tid] = 1.f / ssum;
            } else if (tid < 12) {
                int n = tid - 8;
                float v = __ldg(&b_head[n * HPROW_ + 128]);
                #pragma unroll
                for (int ps = 0; ps < 16; ++ps) v += __ldcg(&g_hp_part[ps][ab][n * 129 + 128]);
                sm.a.ws[n] = sigm_acc(v);
            }
            __syncthreads();
            {
                int n = tid >> 6, h = tid & 63;
                float v = __ldg(&b_head[n * HPROW_ + 64 + h]);
                #pragma unroll
                for (int ps = 0; ps < 16; ++ps) v += __ldcg(&g_hp_part[ps][ab][n * 129 + 64 + h]);
                sm.a.sk[n][h] = v * sm.a.ws[n];
            }
            #pragma unroll
            for (int ms = 0; ms < 2; ++ms)
                #pragma unroll
                for (int key = 0; key < 8; ++key)
                    sm.a.wsm[key][tid * 2 + ms] = __expf(s[ms][key] - sm.a.gm[key]) * sm.a.inv[key];
            __syncthreads();

            const int w = tid >> 5, l = tid & 31;
            const int msub = l >> 3, hb = (l & 7) * 8;
            float skreg[4][8];
            #pragma unroll
            for (int n = 0; n < 4; ++n) {
                float4 a4 = *(const float4*)&sm.a.sk[n][hb];
                float4 c4 = *(const float4*)&sm.a.sk[n][hb + 4];
                skreg[n][0]=a4.x; skreg[n][1]=a4.y; skreg[n][2]=a4.z; skreg[n][3]=a4.w;
                skreg[n][4]=c4.x; skreg[n][5]=c4.y; skreg[n][6]=c4.z; skreg[n][7]=c4.w;
            }
            float racc[4][8];
            #pragma unroll
            for (int n = 0; n < 4; ++n)
                #pragma unroll
                for (int q = 0; q < 8; ++q) racc[n][q] = 0.f;
            #pragma unroll
            for (int it = 0; it < 16; ++it) {
                int ml = it * 32 + w * 4 + msub;
                int m = m0 + ml;
                float* mp = &g_mem[ab][m][hb];                        // block-private: L1-warm
                float4 a4 = *(const float4*)mp;
                float4 c4 = *(const float4*)(mp + 4);
                float mv[8] = {a4.x, a4.y, a4.z, a4.w, c4.x, c4.y, c4.z, c4.w};
                float rw[4], ww[4];
                #pragma unroll
                for (int n = 0; n < 4; ++n) { rw[n] = sm.a.wsm[n][ml]; ww[n] = sm.a.wsm[4 + n][ml]; }
                #pragma unroll
                for (int n = 0; n < 4; ++n)
                    #pragma unroll
                    for (int q = 0; q < 8; ++q) racc[n][q] += rw[n] * mv[q];
                #pragma unroll
                for (int q = 0; q < 8; ++q)
                    mv[q] += ww[0]*skreg[0][q] + ww[1]*skreg[1][q] + ww[2]*skreg[2][q] + ww[3]*skreg[3][q];
                a4.x=mv[0]; a4.y=mv[1]; a4.z=mv[2]; a4.w=mv[3];
                c4.x=mv[4]; c4.y=mv[5]; c4.z=mv[6]; c4.w=mv[7];
                *(float4*)mp = a4;
                *(float4*)(mp + 4) = c4;
            }
            #pragma unroll
            for (int n = 0; n < 4; ++n)
                #pragma unroll
                for (int q = 0; q < 8; ++q) {
                    racc[n][q] += __shfl_xor_sync(0xffffffffu, racc[n][q], 8);
                    racc[n][q] += __shfl_xor_sync(0xffffffffu, racc[n][q], 16);
                }
            if (l < 8) {
                #pragma unroll
                for (int n = 0; n < 4; ++n)
                    #pragma unroll
                    for (int q = 0; q < 8; ++q) sm.a.racc[w][n][hb + q] = racc[n][q];
            }
            __syncthreads();
            {
                int n = tid >> 6, h = tid & 63;
                float ssum = 0.f;
                #pragma unroll
                for (int wr = 0; wr < 8; ++wr) ssum += sm.a.racc[wr][n][h];
                g_read_part[t][mq][ab][n * 64 + h] = ssum;
            }
        }
        gridbar(4*t + 3);
    }
}

// ---------------- final output GEMM: outputs[b][t][o] ----------------
__global__ void k_out(const float* __restrict__ b_out, float* __restrict__ out) {
    const int m0 = blockIdx.x * 32, nc = blockIdx.y;
    const int tid = threadIdx.x;
    __shared__ float a_sh[32][64];
    const int n_l = tid & 63, mg = tid >> 6;
    const int n = nc * 64 + n_l;
    float acc[8];
    #pragma unroll
    for (int r = 0; r < 8; ++r) acc[r] = 0.f;
    for (int kt = 0; kt < 12; ++kt) {
        __syncthreads();
        #pragma unroll
        for (int e = 0; e < 8; ++e) {
            int lidx = e * 256 + tid;
            int mrow = lidx >> 6, kk = lidx & 63;
            int m = m0 + mrow;
            int ts = m >> 5, bb = m & 31;
            int gk = kt * 64 + kk;
            float v;
            if (gk < 512) v = g_hist_h[ts][bb][gk];
            else {
                int r = gk - 512;
                v = g_read_part[ts][0][bb][r] + g_read_part[ts][1][bb][r]
                  + g_read_part[ts][2][bb][r] + g_read_part[ts][3][bb][r];
            }
            a_sh[mrow][kk] = v;
        }
        __syncthreads();
        #pragma unroll 4
        for (int kk = 0; kk < 64; ++kk) {
            float wv = g_WoT[(kt * 64 + kk) * O_ + n];
            #pragma unroll
            for (int r = 0; r < 8; ++r) acc[r] += a_sh[mg * 8 + r][kk] * wv;
        }
    }
    float bo = b_out[n];
    #pragma unroll
    for (int r = 0; r < 8; ++r) {
        int m = m0 + mg * 8 + r;
        int ts = m >> 5, bb = m & 31;
        out[(bb * T_ + ts) * O_ + n] = acc[r] + bo;
    }
}

// ---------------- final state copy: mem, h, c into d_out ----------------
__global__ void k_final(float* __restrict__ out) {
    const int OUT_N = B_ * T_ * O_;            // 262144
    const int NMEM  = B_ * MS_ * HS_;          // 4194304
    const int total = NMEM + 2 * B_ * H_;
    for (int i = blockIdx.x * blockDim.x + threadIdx.x; i < total; i += gridDim.x * blockDim.x) {
        if (i < NMEM)                 out[OUT_N + i] = (&g_mem[0][0][0])[i];
        else if (i < NMEM + B_ * H_)  out[OUT_N + i] = g_h[i - NMEM];
        else                          out[OUT_N + i] = g_c[i - NMEM - B_ * H_];
    }
}

extern "C" void kernel_launch(void* const* d_in, const int* in_sizes, int n_in,
                              void* d_out, int out_size) {
    const float* x      = (const float*)d_in[0];
    const float* W_ih   = (const float*)d_in[1];
    const float* W_hh   = (const float*)d_in[2];
    const float* b_ih   = (const float*)d_in[3];
    const float* b_hh   = (const float*)d_in[4];
    const float* W_head = (const float*)d_in[5];
    const float* b_head = (const float*)d_in[6];
    const float* W_out  = (const float*)d_in[7];
    const float* b_out  = (const float*)d_in[8];
    float* out = (float*)d_out;

    k_zero<<<2048, 256>>>();
    k_trA<<<dim3(32, 64), dim3(32, 8)>>>(W_ih, W_hh);
    k_trH<<<dim3(16, 17), dim3(32, 8)>>>(W_head);
    k_trO<<<dim3(24, 8),  dim3(32, 8)>>>(W_out);
    k_steps<<<NBLK, 256>>>(x, b_ih, b_hh, b_head);
    k_out<<<dim3(32, 4), 256>>>(b_out, out);
    k_final<<<2048, 256>>>(out);
}